// round 6
// baseline (speedup 1.0000x reference)
#include <cuda_runtime.h>
#include <cuda_bf16.h>

#define NN 50000
#define NE 800000
#define HID 64
#define NB 49   // scan blocks: ceil(50000/1024)

// ---------------- scratch (device globals; no allocation allowed) -------------
__device__ float g_bufA[NN * HID];
__device__ float g_bufB[NN * HID];
__device__ float g_z[NN];
__device__ float g_dinv[NN];
__device__ int   g_cnt[NN];
__device__ int   g_rowptr[NN + 1];
__device__ int   g_fill[NN];
__device__ int2  g_cw[NE];           // packed {src, __float_as_int(w)} per CSR slot
__device__ int   g_bsum[NB];
__device__ int   g_boff[NB];

// ---------------- CSR build --------------------------------------------------
__global__ void k_zero_cnt() {
    int i = blockIdx.x * blockDim.x + threadIdx.x;
    if (i < NN) g_cnt[i] = 0;
}

__global__ void k_count(const int* __restrict__ ei) {
    int e = blockIdx.x * blockDim.x + threadIdx.x;
    if (e < NE) atomicAdd(&g_cnt[ei[NE + e]], 1);
}

__global__ void k_dinv() {
    int i = blockIdx.x * blockDim.x + threadIdx.x;
    if (i < NN) g_dinv[i] = rsqrtf((float)(g_cnt[i] + 1));  // +1 self loop
}

__global__ void k_blocksum() {
    __shared__ int sw[8];
    int base = blockIdx.x * 1024 + threadIdx.x * 4;
    int v = 0;
    #pragma unroll
    for (int k = 0; k < 4; k++) {
        int i = base + k;
        if (i < NN) v += g_cnt[i];
    }
    #pragma unroll
    for (int o = 16; o; o >>= 1) v += __shfl_xor_sync(0xffffffffu, v, o);
    if ((threadIdx.x & 31) == 0) sw[threadIdx.x >> 5] = v;
    __syncthreads();
    if (threadIdx.x == 0) {
        int s = 0;
        #pragma unroll
        for (int w = 0; w < 8; w++) s += sw[w];
        g_bsum[blockIdx.x] = s;
    }
}

__global__ void k_scanb() {
    int s = 0;
    for (int b = 0; b < NB; b++) { g_boff[b] = s; s += g_bsum[b]; }
    g_rowptr[NN] = s;
}

__global__ void k_scanfinal() {
    __shared__ int swarp[32];
    int lane = threadIdx.x & 31, wid = threadIdx.x >> 5;
    int i = blockIdx.x * 1024 + threadIdx.x;
    int v = (i < NN) ? g_cnt[i] : 0;
    int incl = v;
    #pragma unroll
    for (int o = 1; o < 32; o <<= 1) {
        int t = __shfl_up_sync(0xffffffffu, incl, o);
        if (lane >= o) incl += t;
    }
    if (lane == 31) swarp[wid] = incl;
    __syncthreads();
    if (wid == 0) {
        int s = swarp[lane];
        int si = s;
        #pragma unroll
        for (int o = 1; o < 32; o <<= 1) {
            int t = __shfl_up_sync(0xffffffffu, si, o);
            if (lane >= o) si += t;
        }
        swarp[lane] = si - s;
    }
    __syncthreads();
    if (i < NN) {
        int excl = incl - v + swarp[wid] + g_boff[blockIdx.x];
        g_rowptr[i] = excl;
        g_fill[i]   = excl;
    }
}

__global__ void k_scatter(const int* __restrict__ ei) {
    int e = blockIdx.x * blockDim.x + threadIdx.x;
    if (e < NE) {
        int s = ei[e];
        int d = ei[NE + e];
        int pos = atomicAdd(&g_fill[d], 1);
        float w = g_dinv[s] * g_dinv[d];
        g_cw[pos] = make_int2(s, __float_as_int(w));
    }
}

// ---------------- layer 0: aggregate raw x (4-wide), warp/node, edge-parallel --
__global__ void k_agg_x(const float* __restrict__ x) {
    int warp = (blockIdx.x * blockDim.x + threadIdx.x) >> 5;
    int lane = threadIdx.x & 31;
    if (warp >= NN) return;
    int n = warp;
    const float4* x4 = (const float4*)x;
    float4 acc = make_float4(0.f, 0.f, 0.f, 0.f);
    int beg = g_rowptr[n], end = g_rowptr[n + 1];
    for (int j = beg + lane; j < end; j += 32) {
        int2 cw = g_cw[j];
        float w = __int_as_float(cw.y);
        float4 v = __ldg(&x4[cw.x]);
        acc.x = fmaf(w, v.x, acc.x);
        acc.y = fmaf(w, v.y, acc.y);
        acc.z = fmaf(w, v.z, acc.z);
        acc.w = fmaf(w, v.w, acc.w);
    }
    #pragma unroll
    for (int o = 16; o; o >>= 1) {
        acc.x += __shfl_xor_sync(0xffffffffu, acc.x, o);
        acc.y += __shfl_xor_sync(0xffffffffu, acc.y, o);
        acc.z += __shfl_xor_sync(0xffffffffu, acc.z, o);
        acc.w += __shfl_xor_sync(0xffffffffu, acc.w, o);
    }
    if (lane == 0) {
        float di = g_dinv[n], ws = di * di;
        float4 sv = x4[n];
        acc.x = fmaf(ws, sv.x, acc.x);
        acc.y = fmaf(ws, sv.y, acc.y);
        acc.z = fmaf(ws, sv.z, acc.z);
        acc.w = fmaf(ws, sv.w, acc.w);
        ((float4*)g_bufA)[n] = acc;
    }
}

// h0 = relu( y[NN,4] @ W_in[4,64] + b )  -> bufB
__global__ void k_gemm_in(const float* __restrict__ W, const float* __restrict__ bias) {
    __shared__ float Ws[4 * HID];
    __shared__ float Bs[HID];
    if (threadIdx.x < 256) Ws[threadIdx.x] = W[threadIdx.x];
    if (threadIdx.x < HID) Bs[threadIdx.x] = bias[threadIdx.x];
    __syncthreads();
    int t = blockIdx.x * blockDim.x + threadIdx.x;
    int n = t >> 6, f = t & 63;
    if (n < NN) {
        float4 y = ((const float4*)g_bufA)[n];
        float acc = Bs[f];
        acc = fmaf(y.x, Ws[0 * HID + f], acc);
        acc = fmaf(y.y, Ws[1 * HID + f], acc);
        acc = fmaf(y.z, Ws[2 * HID + f], acc);
        acc = fmaf(y.w, Ws[3 * HID + f], acc);
        g_bufB[n * HID + f] = fmaxf(acc, 0.f);
    }
}

// ---------------- hidden dense: bufB @ W -> bufA ------------------------------
__global__ void k_gemm64(const float* __restrict__ W) {
    __shared__ float Ws[HID * HID];
    __shared__ __align__(16) float Hs[4 * HID];
    for (int i = threadIdx.x; i < HID * HID; i += blockDim.x) Ws[i] = W[i];
    int nodeBase = blockIdx.x * 64;
    int f  = threadIdx.x & 63;
    int nl = threadIdx.x >> 6;
    for (int c = 0; c < 64; c += 4) {
        __syncthreads();
        int n = nodeBase + c + nl;
        Hs[nl * HID + f] = (n < NN) ? g_bufB[n * HID + f] : 0.f;
        __syncthreads();
        if (n < NN) {
            const float4* H4 = (const float4*)&Hs[nl * HID];
            float acc = 0.f;
            #pragma unroll
            for (int k4 = 0; k4 < 16; k4++) {
                float4 h = H4[k4];
                acc = fmaf(h.x, Ws[(4 * k4 + 0) * HID + f], acc);
                acc = fmaf(h.y, Ws[(4 * k4 + 1) * HID + f], acc);
                acc = fmaf(h.z, Ws[(4 * k4 + 2) * HID + f], acc);
                acc = fmaf(h.w, Ws[(4 * k4 + 3) * HID + f], acc);
            }
            g_bufA[n * HID + f] = acc;
        }
    }
}

// ---------- hidden aggregation: warp/node, float2 lanes, x4 unroll ------------
// LAST=false: bufB = relu(agg + bias)
// LAST=true : g_z = relu(agg + bias) . Wout     (gemm_out fused)
template <bool LAST>
__global__ void k_agg64(const float* __restrict__ bias, const float* __restrict__ Wout) {
    int warp = (blockIdx.x * blockDim.x + threadIdx.x) >> 5;
    int lane = threadIdx.x & 31;
    if (warp >= NN) return;
    int n = warp;
    const float2* A2 = (const float2*)g_bufA;
    float ax = 0.f, ay = 0.f;
    int beg = g_rowptr[n], end = g_rowptr[n + 1];
    int j = beg;
    for (; j + 3 < end; j += 4) {
        int2 c0 = g_cw[j];
        int2 c1 = g_cw[j + 1];
        int2 c2 = g_cw[j + 2];
        int2 c3 = g_cw[j + 3];
        float2 v0 = __ldg(&A2[c0.x * 32 + lane]);
        float2 v1 = __ldg(&A2[c1.x * 32 + lane]);
        float2 v2 = __ldg(&A2[c2.x * 32 + lane]);
        float2 v3 = __ldg(&A2[c3.x * 32 + lane]);
        float w0 = __int_as_float(c0.y), w1 = __int_as_float(c1.y);
        float w2 = __int_as_float(c2.y), w3 = __int_as_float(c3.y);
        ax = fmaf(w0, v0.x, ax); ay = fmaf(w0, v0.y, ay);
        ax = fmaf(w1, v1.x, ax); ay = fmaf(w1, v1.y, ay);
        ax = fmaf(w2, v2.x, ax); ay = fmaf(w2, v2.y, ay);
        ax = fmaf(w3, v3.x, ax); ay = fmaf(w3, v3.y, ay);
    }
    for (; j < end; j++) {
        int2 c = g_cw[j];
        float w = __int_as_float(c.y);
        float2 v = __ldg(&A2[c.x * 32 + lane]);
        ax = fmaf(w, v.x, ax);
        ay = fmaf(w, v.y, ay);
    }
    float di = g_dinv[n], ws = di * di;
    float2 sv = A2[n * 32 + lane];
    float2 b2 = ((const float2*)bias)[lane];
    ax = fmaxf(fmaf(ws, sv.x, ax) + b2.x, 0.f);
    ay = fmaxf(fmaf(ws, sv.y, ay) + b2.y, 0.f);
    if (!LAST) {
        ((float2*)g_bufB)[n * 32 + lane] = make_float2(ax, ay);
    } else {
        float2 w2 = ((const float2*)Wout)[lane];
        float s = ax * w2.x + ay * w2.y;
        #pragma unroll
        for (int o = 16; o; o >>= 1) s += __shfl_xor_sync(0xffffffffu, s, o);
        if (lane == 0) g_z[n] = s;
    }
}

// ---------------- final scalar aggregation ------------------------------------
__global__ void k_agg_scalar(float* __restrict__ out, const float* __restrict__ b_out) {
    int n = blockIdx.x * blockDim.x + threadIdx.x;
    if (n < NN) {
        float acc = 0.f;
        int beg = g_rowptr[n], end = g_rowptr[n + 1];
        for (int j = beg; j < end; j++) {
            int2 c = g_cw[j];
            acc = fmaf(__int_as_float(c.y), __ldg(&g_z[c.x]), acc);
        }
        float di = g_dinv[n];
        acc = fmaf(di * di, g_z[n], acc);
        out[n] = acc + b_out[0];
    }
}

// ---------------- launch ------------------------------------------------------
extern "C" void kernel_launch(void* const* d_in, const int* in_sizes, int n_in,
                              void* d_out, int out_size) {
    const float* x     = (const float*)d_in[0];
    const int*   ei    = (const int*)d_in[1];
    const float* W_in  = (const float*)d_in[2];
    const float* b_in  = (const float*)d_in[3];
    const float* W_h   = (const float*)d_in[4];
    const float* b_h   = (const float*)d_in[5];
    const float* W_out = (const float*)d_in[6];
    const float* b_out = (const float*)d_in[7];
    float*       out   = (float*)d_out;

    const int TB = 256;
    const int gN  = (NN + TB - 1) / TB;
    const int gE  = (NE + TB - 1) / TB;
    const int gNF = (NN * HID + TB - 1) / TB;
    const int gW  = (NN * 32 + TB - 1) / TB;
    const int gG  = (NN + 63) / 64;

    // CSR build
    k_zero_cnt<<<gN, TB>>>();
    k_count<<<gE, TB>>>(ei);
    k_dinv<<<gN, TB>>>();
    k_blocksum<<<NB, 256>>>();
    k_scanb<<<1, 1>>>();
    k_scanfinal<<<NB, 1024>>>();
    k_scatter<<<gE, TB>>>(ei);

    // layer 0: aggregate x (4-wide, warp/node), then fused gemm+bias+relu
    k_agg_x<<<gW, TB>>>(x);
    k_gemm_in<<<gNF, TB>>>(W_in, b_in);

    // hidden layers 1-2
    for (int l = 0; l < 2; l++) {
        k_gemm64<<<gG, TB>>>(W_h + l * HID * HID);
        k_agg64<false><<<gW, TB>>>(b_h + l * HID, nullptr);
    }
    // hidden layer 3 with fused output GEMM
    k_gemm64<<<gG, TB>>>(W_h + 2 * HID * HID);
    k_agg64<true><<<gW, TB>>>(b_h + 2 * HID, W_out);

    // final scalar aggregation
    k_agg_scalar<<<gN, TB>>>(out, b_out);
}

// round 7
// speedup vs baseline: 1.0761x; 1.0761x over previous
#include <cuda_runtime.h>
#include <cuda_fp16.h>
#include <cuda_bf16.h>

#define NN 50000
#define NE 800000
#define HID 64
#define NB 49   // scan blocks: ceil(50000/1024)

// ---------------- scratch (device globals; no allocation allowed) -------------
__device__ float   g_bufA[NN * HID];     // layer-0 staging (fp32)
__device__ __half2 g_bufAh[NN * HID/2];  // hidden GEMM output, fp16 rows (gather src)
__device__ float   g_bufB[NN * HID];     // aggregation output (fp32)
__device__ float   g_z[NN];
__device__ float   g_dinv[NN];
__device__ int     g_cnt[NN];
__device__ int     g_rowptr[NN + 1];
__device__ int     g_fill[NN];
__device__ int     g_col[NE];
__device__ float   g_wt[NE];
__device__ int     g_bsum[NB];
__device__ int     g_boff[NB];

// ---------------- CSR build --------------------------------------------------
__global__ void k_zero_cnt() {
    int i = blockIdx.x * blockDim.x + threadIdx.x;
    if (i < NN) g_cnt[i] = 0;
}

__global__ void k_count(const int* __restrict__ ei) {
    int e = blockIdx.x * blockDim.x + threadIdx.x;
    if (e < NE) atomicAdd(&g_cnt[ei[NE + e]], 1);
}

__global__ void k_dinv() {
    int i = blockIdx.x * blockDim.x + threadIdx.x;
    if (i < NN) g_dinv[i] = rsqrtf((float)(g_cnt[i] + 1));  // +1 self loop
}

__global__ void k_blocksum() {
    __shared__ int sw[8];
    int base = blockIdx.x * 1024 + threadIdx.x * 4;
    int v = 0;
    #pragma unroll
    for (int k = 0; k < 4; k++) {
        int i = base + k;
        if (i < NN) v += g_cnt[i];
    }
    #pragma unroll
    for (int o = 16; o; o >>= 1) v += __shfl_xor_sync(0xffffffffu, v, o);
    if ((threadIdx.x & 31) == 0) sw[threadIdx.x >> 5] = v;
    __syncthreads();
    if (threadIdx.x == 0) {
        int s = 0;
        #pragma unroll
        for (int w = 0; w < 8; w++) s += sw[w];
        g_bsum[blockIdx.x] = s;
    }
}

__global__ void k_scanb() {
    int s = 0;
    for (int b = 0; b < NB; b++) { g_boff[b] = s; s += g_bsum[b]; }
    g_rowptr[NN] = s;
}

__global__ void k_scanfinal() {
    __shared__ int swarp[32];
    int lane = threadIdx.x & 31, wid = threadIdx.x >> 5;
    int i = blockIdx.x * 1024 + threadIdx.x;
    int v = (i < NN) ? g_cnt[i] : 0;
    int incl = v;
    #pragma unroll
    for (int o = 1; o < 32; o <<= 1) {
        int t = __shfl_up_sync(0xffffffffu, incl, o);
        if (lane >= o) incl += t;
    }
    if (lane == 31) swarp[wid] = incl;
    __syncthreads();
    if (wid == 0) {
        int s = swarp[lane];
        int si = s;
        #pragma unroll
        for (int o = 1; o < 32; o <<= 1) {
            int t = __shfl_up_sync(0xffffffffu, si, o);
            if (lane >= o) si += t;
        }
        swarp[lane] = si - s;
    }
    __syncthreads();
    if (i < NN) {
        int excl = incl - v + swarp[wid] + g_boff[blockIdx.x];
        g_rowptr[i] = excl;
        g_fill[i]   = excl;
    }
}

__global__ void k_scatter(const int* __restrict__ ei) {
    int e = blockIdx.x * blockDim.x + threadIdx.x;
    if (e < NE) {
        int s = ei[e];
        int d = ei[NE + e];
        int pos = atomicAdd(&g_fill[d], 1);
        g_col[pos] = s;
        g_wt[pos]  = g_dinv[s] * g_dinv[d];
    }
}

// ---------------- layer 0: aggregate raw x (4-wide), warp/node, edge-parallel --
__global__ void k_agg_x(const float* __restrict__ x) {
    int warp = (blockIdx.x * blockDim.x + threadIdx.x) >> 5;
    int lane = threadIdx.x & 31;
    if (warp >= NN) return;
    int n = warp;
    const float4* x4 = (const float4*)x;
    float4 acc = make_float4(0.f, 0.f, 0.f, 0.f);
    int beg = g_rowptr[n], end = g_rowptr[n + 1];
    for (int j = beg + lane; j < end; j += 32) {
        int s = g_col[j];
        float w = g_wt[j];
        float4 v = __ldg(&x4[s]);
        acc.x = fmaf(w, v.x, acc.x);
        acc.y = fmaf(w, v.y, acc.y);
        acc.z = fmaf(w, v.z, acc.z);
        acc.w = fmaf(w, v.w, acc.w);
    }
    #pragma unroll
    for (int o = 16; o; o >>= 1) {
        acc.x += __shfl_xor_sync(0xffffffffu, acc.x, o);
        acc.y += __shfl_xor_sync(0xffffffffu, acc.y, o);
        acc.z += __shfl_xor_sync(0xffffffffu, acc.z, o);
        acc.w += __shfl_xor_sync(0xffffffffu, acc.w, o);
    }
    if (lane == 0) {
        float di = g_dinv[n], ws = di * di;
        float4 sv = x4[n];
        acc.x = fmaf(ws, sv.x, acc.x);
        acc.y = fmaf(ws, sv.y, acc.y);
        acc.z = fmaf(ws, sv.z, acc.z);
        acc.w = fmaf(ws, sv.w, acc.w);
        ((float4*)g_bufA)[n] = acc;
    }
}

// h0 = relu( y[NN,4] @ W_in[4,64] + b )  -> bufB (fp32)
__global__ void k_gemm_in(const float* __restrict__ W, const float* __restrict__ bias) {
    __shared__ float Ws[4 * HID];
    __shared__ float Bs[HID];
    if (threadIdx.x < 256) Ws[threadIdx.x] = W[threadIdx.x];
    if (threadIdx.x < HID) Bs[threadIdx.x] = bias[threadIdx.x];
    __syncthreads();
    int t = blockIdx.x * blockDim.x + threadIdx.x;
    int n = t >> 6, f = t & 63;
    if (n < NN) {
        float4 y = ((const float4*)g_bufA)[n];
        float acc = Bs[f];
        acc = fmaf(y.x, Ws[0 * HID + f], acc);
        acc = fmaf(y.y, Ws[1 * HID + f], acc);
        acc = fmaf(y.z, Ws[2 * HID + f], acc);
        acc = fmaf(y.w, Ws[3 * HID + f], acc);
        g_bufB[n * HID + f] = fmaxf(acc, 0.f);
    }
}

// ---------------- hidden dense: bufB(fp32) @ W -> bufAh (fp16 rows) ------------
__global__ void k_gemm64(const float* __restrict__ W) {
    __shared__ float Ws[HID * HID];
    __shared__ __align__(16) float Hs[4 * HID];
    for (int i = threadIdx.x; i < HID * HID; i += blockDim.x) Ws[i] = W[i];
    int nodeBase = blockIdx.x * 64;
    int f  = threadIdx.x & 63;
    int nl = threadIdx.x >> 6;
    for (int c = 0; c < 64; c += 4) {
        __syncthreads();
        int n = nodeBase + c + nl;
        Hs[nl * HID + f] = (n < NN) ? g_bufB[n * HID + f] : 0.f;
        __syncthreads();
        if (n < NN) {
            const float4* H4 = (const float4*)&Hs[nl * HID];
            float acc = 0.f;
            #pragma unroll
            for (int k4 = 0; k4 < 16; k4++) {
                float4 h = H4[k4];
                acc = fmaf(h.x, Ws[(4 * k4 + 0) * HID + f], acc);
                acc = fmaf(h.y, Ws[(4 * k4 + 1) * HID + f], acc);
                acc = fmaf(h.z, Ws[(4 * k4 + 2) * HID + f], acc);
                acc = fmaf(h.w, Ws[(4 * k4 + 3) * HID + f], acc);
            }
            // pair lanes (f even/odd) into one half2 store at [n*32 + f/2]
            float accHi = __shfl_down_sync(0xffffffffu, acc, 1);
            if ((f & 1) == 0)
                g_bufAh[n * 32 + (f >> 1)] = __floats2half2_rn(acc, accHi);
        }
    }
}

// ---------- hidden aggregation: warp/node, half2 gathers, fp32 accumulate ------
// lane handles features (2*lane, 2*lane+1)
__global__ void k_agg64(const float* __restrict__ bias) {
    int warp = (blockIdx.x * blockDim.x + threadIdx.x) >> 5;
    int lane = threadIdx.x & 31;
    if (warp >= NN) return;
    int n = warp;
    float ax = 0.f, ay = 0.f;
    int beg = g_rowptr[n], end = g_rowptr[n + 1];
    for (int j = beg; j < end; j++) {
        int s = g_col[j];
        float w = g_wt[j];
        float2 v = __half22float2(__ldg(&g_bufAh[s * 32 + lane]));
        ax = fmaf(w, v.x, ax);
        ay = fmaf(w, v.y, ay);
    }
    float di = g_dinv[n], ws = di * di;
    float2 sv = __half22float2(g_bufAh[n * 32 + lane]);
    float2 b2 = ((const float2*)bias)[lane];
    ax = fmaxf(fmaf(ws, sv.x, ax) + b2.x, 0.f);
    ay = fmaxf(fmaf(ws, sv.y, ay) + b2.y, 0.f);
    ((float2*)g_bufB)[n * 32 + lane] = make_float2(ax, ay);
}

// ---------------- output layer ------------------------------------------------
__global__ void k_gemm_out(const float* __restrict__ Wout) {
    int warp = (blockIdx.x * blockDim.x + threadIdx.x) >> 5;
    int lane = threadIdx.x & 31;
    if (warp < NN) {
        float a = g_bufB[warp * HID + lane] * Wout[lane]
                + g_bufB[warp * HID + lane + 32] * Wout[lane + 32];
        #pragma unroll
        for (int o = 16; o; o >>= 1) a += __shfl_xor_sync(0xffffffffu, a, o);
        if (lane == 0) g_z[warp] = a;
    }
}

__global__ void k_agg_scalar(float* __restrict__ out, const float* __restrict__ b_out) {
    int n = blockIdx.x * blockDim.x + threadIdx.x;
    if (n < NN) {
        float acc = 0.f;
        int beg = g_rowptr[n], end = g_rowptr[n + 1];
        for (int j = beg; j < end; j++) acc = fmaf(g_wt[j], __ldg(&g_z[g_col[j]]), acc);
        float di = g_dinv[n];
        acc = fmaf(di * di, g_z[n], acc);
        out[n] = acc + b_out[0];
    }
}

// ---------------- launch ------------------------------------------------------
extern "C" void kernel_launch(void* const* d_in, const int* in_sizes, int n_in,
                              void* d_out, int out_size) {
    const float* x     = (const float*)d_in[0];
    const int*   ei    = (const int*)d_in[1];
    const float* W_in  = (const float*)d_in[2];
    const float* b_in  = (const float*)d_in[3];
    const float* W_h   = (const float*)d_in[4];
    const float* b_h   = (const float*)d_in[5];
    const float* W_out = (const float*)d_in[6];
    const float* b_out = (const float*)d_in[7];
    float*       out   = (float*)d_out;

    const int TB = 256;
    const int gN  = (NN + TB - 1) / TB;
    const int gE  = (NE + TB - 1) / TB;
    const int gNF = (NN * HID + TB - 1) / TB;
    const int gW  = (NN * 32 + TB - 1) / TB;
    const int gG  = (NN + 63) / 64;

    // CSR build
    k_zero_cnt<<<gN, TB>>>();
    k_count<<<gE, TB>>>(ei);
    k_dinv<<<gN, TB>>>();
    k_blocksum<<<NB, 256>>>();
    k_scanb<<<1, 1>>>();
    k_scanfinal<<<NB, 1024>>>();
    k_scatter<<<gE, TB>>>(ei);

    // layer 0: aggregate x (4-wide, warp/node), then fused gemm+bias+relu
    k_agg_x<<<gW, TB>>>(x);
    k_gemm_in<<<gNF, TB>>>(W_in, b_in);

    // hidden layers
    for (int l = 0; l < 3; l++) {
        k_gemm64<<<gG, TB>>>(W_h + l * HID * HID);
        k_agg64<<<gW, TB>>>(b_h + l * HID);
    }

    // output layer
    k_gemm_out<<<gW, TB>>>(W_out);
    k_agg_scalar<<<gN, TB>>>(out, b_out);
}

// round 9
// speedup vs baseline: 1.1464x; 1.0654x over previous
#include <cuda_runtime.h>
#include <cuda_fp16.h>
#include <cuda_bf16.h>

#define NN 50000
#define NE 800000
#define HID 64
#define NB 49   // scan blocks: ceil(50000/1024)

// ---------------- scratch (device globals; no allocation allowed) -------------
__device__ float   g_xs[NN * 4];         // dinv[n] * x[n]  (pre-scaled input)
__device__ float   g_bufA[NN * 4];       // layer-0 aggregated input (4-wide)
__device__ __half2 g_bufAh[NN * HID/2];  // hidden GEMM output, pre-scaled fp16 rows
__device__ float   g_bufB[NN * HID];     // aggregation output (fp32)
__device__ float   g_z[NN];              // pre-scaled final scalar  dinv[n]*z[n]
__device__ float   g_dinv[NN];
__device__ int     g_cnt[NN];
__device__ int     g_rowptr[NN + 1];
__device__ int     g_fill[NN];
__device__ int     g_col[NE];
__device__ int     g_bsum[NB];
__device__ int     g_boff[NB];

// ---------------- CSR build --------------------------------------------------
__global__ void k_zero_cnt() {
    int i = blockIdx.x * blockDim.x + threadIdx.x;
    if (i < NN) g_cnt[i] = 0;
}

__global__ void k_count(const int* __restrict__ ei) {
    int e = blockIdx.x * blockDim.x + threadIdx.x;
    if (e < NE) atomicAdd(&g_cnt[ei[NE + e]], 1);
}

// dinv + pre-scaled input xs = dinv[n]*x[n]
__global__ void k_dinv(const float* __restrict__ x) {
    int i = blockIdx.x * blockDim.x + threadIdx.x;
    if (i < NN) {
        float di = rsqrtf((float)(g_cnt[i] + 1));  // +1 self loop
        g_dinv[i] = di;
        float4 v = ((const float4*)x)[i];
        v.x *= di; v.y *= di; v.z *= di; v.w *= di;
        ((float4*)g_xs)[i] = v;
    }
}

__global__ void k_blocksum() {
    __shared__ int sw[8];
    int base = blockIdx.x * 1024 + threadIdx.x * 4;
    int v = 0;
    #pragma unroll
    for (int k = 0; k < 4; k++) {
        int i = base + k;
        if (i < NN) v += g_cnt[i];
    }
    #pragma unroll
    for (int o = 16; o; o >>= 1) v += __shfl_xor_sync(0xffffffffu, v, o);
    if ((threadIdx.x & 31) == 0) sw[threadIdx.x >> 5] = v;
    __syncthreads();
    if (threadIdx.x == 0) {
        int s = 0;
        #pragma unroll
        for (int w = 0; w < 8; w++) s += sw[w];
        g_bsum[blockIdx.x] = s;
    }
}

__global__ void k_scanb() {
    int s = 0;
    for (int b = 0; b < NB; b++) { g_boff[b] = s; s += g_bsum[b]; }
    g_rowptr[NN] = s;
}

__global__ void k_scanfinal() {
    __shared__ int swarp[32];
    int lane = threadIdx.x & 31, wid = threadIdx.x >> 5;
    int i = blockIdx.x * 1024 + threadIdx.x;
    int v = (i < NN) ? g_cnt[i] : 0;
    int incl = v;
    #pragma unroll
    for (int o = 1; o < 32; o <<= 1) {
        int t = __shfl_up_sync(0xffffffffu, incl, o);
        if (lane >= o) incl += t;
    }
    if (lane == 31) swarp[wid] = incl;
    __syncthreads();
    if (wid == 0) {
        int s = swarp[lane];
        int si = s;
        #pragma unroll
        for (int o = 1; o < 32; o <<= 1) {
            int t = __shfl_up_sync(0xffffffffu, si, o);
            if (lane >= o) si += t;
        }
        swarp[lane] = si - s;
    }
    __syncthreads();
    if (i < NN) {
        int excl = incl - v + swarp[wid] + g_boff[blockIdx.x];
        g_rowptr[i] = excl;
        g_fill[i]   = excl;
    }
}

__global__ void k_scatter(const int* __restrict__ ei) {
    int e = blockIdx.x * blockDim.x + threadIdx.x;
    if (e < NE) {
        int s = ei[e];
        int d = ei[NE + e];
        int pos = atomicAdd(&g_fill[d], 1);
        g_col[pos] = s;
    }
}

// ------- layer 0: y[n] = dinv[n]*( sum_e xs[src_e] + xs[n] ), 4-wide ----------
__global__ void k_agg_x() {
    int warp = (blockIdx.x * blockDim.x + threadIdx.x) >> 5;
    int lane = threadIdx.x & 31;
    if (warp >= NN) return;
    int n = warp;
    const float4* xs4 = (const float4*)g_xs;
    float4 acc = make_float4(0.f, 0.f, 0.f, 0.f);
    int beg = g_rowptr[n], end = g_rowptr[n + 1];
    for (int j = beg + lane; j < end; j += 32) {
        float4 v = __ldg(&xs4[g_col[j]]);
        acc.x += v.x; acc.y += v.y; acc.z += v.z; acc.w += v.w;
    }
    #pragma unroll
    for (int o = 16; o; o >>= 1) {
        acc.x += __shfl_xor_sync(0xffffffffu, acc.x, o);
        acc.y += __shfl_xor_sync(0xffffffffu, acc.y, o);
        acc.z += __shfl_xor_sync(0xffffffffu, acc.z, o);
        acc.w += __shfl_xor_sync(0xffffffffu, acc.w, o);
    }
    if (lane == 0) {
        float di = g_dinv[n];
        float4 sv = xs4[n];
        acc.x = di * (acc.x + sv.x);
        acc.y = di * (acc.y + sv.y);
        acc.z = di * (acc.z + sv.z);
        acc.w = di * (acc.w + sv.w);
        ((float4*)g_bufA)[n] = acc;
    }
}

// h0 = relu( y[NN,4] @ W_in[4,64] + b )  -> bufB (fp32)
__global__ void k_gemm_in(const float* __restrict__ W, const float* __restrict__ bias) {
    __shared__ float Ws[4 * HID];
    __shared__ float Bs[HID];
    if (threadIdx.x < 256) Ws[threadIdx.x] = W[threadIdx.x];
    if (threadIdx.x < HID) Bs[threadIdx.x] = bias[threadIdx.x];
    __syncthreads();
    int t = blockIdx.x * blockDim.x + threadIdx.x;
    int n = t >> 6, f = t & 63;
    if (n < NN) {
        float4 y = ((const float4*)g_bufA)[n];
        float acc = Bs[f];
        acc = fmaf(y.x, Ws[0 * HID + f], acc);
        acc = fmaf(y.y, Ws[1 * HID + f], acc);
        acc = fmaf(y.z, Ws[2 * HID + f], acc);
        acc = fmaf(y.w, Ws[3 * HID + f], acc);
        g_bufB[n * HID + f] = fmaxf(acc, 0.f);
    }
}

// ------ hidden dense: bufB(fp32) @ W, pre-scaled by dinv[n] -> bufAh fp16 ------
__global__ void k_gemm64(const float* __restrict__ W) {
    __shared__ float Ws[HID * HID];
    __shared__ __align__(16) float Hs[4 * HID];
    for (int i = threadIdx.x; i < HID * HID; i += blockDim.x) Ws[i] = W[i];
    int nodeBase = blockIdx.x * 64;
    int f  = threadIdx.x & 63;
    int nl = threadIdx.x >> 6;
    for (int c = 0; c < 64; c += 4) {
        __syncthreads();
        int n = nodeBase + c + nl;
        Hs[nl * HID + f] = (n < NN) ? g_bufB[n * HID + f] : 0.f;
        __syncthreads();
        if (n < NN) {
            const float4* H4 = (const float4*)&Hs[nl * HID];
            float acc = 0.f;
            #pragma unroll
            for (int k4 = 0; k4 < 16; k4++) {
                float4 h = H4[k4];
                acc = fmaf(h.x, Ws[(4 * k4 + 0) * HID + f], acc);
                acc = fmaf(h.y, Ws[(4 * k4 + 1) * HID + f], acc);
                acc = fmaf(h.z, Ws[(4 * k4 + 2) * HID + f], acc);
                acc = fmaf(h.w, Ws[(4 * k4 + 3) * HID + f], acc);
            }
            acc *= g_dinv[n];  // pre-scale: hs = dinv[n] * (h @ W)
            float accHi = __shfl_down_sync(0xffffffffu, acc, 1);
            if ((f & 1) == 0)
                g_bufAh[n * 32 + (f >> 1)] = __floats2half2_rn(acc, accHi);
        }
    }
}

// ---- hidden aggregation: warp/node, unweighted half2 gathers, fp32 accum -----
// out_feat = relu( dinv[n]*(Sum hs[src] + hs[n]) + bias )
// LAST=false: -> bufB (fp32)
// LAST=true : g_z[n] = dinv[n] * (out_feat . Wout)
template <bool LAST>
__global__ void k_agg64(const float* __restrict__ bias, const float* __restrict__ Wout) {
    int warp = (blockIdx.x * blockDim.x + threadIdx.x) >> 5;
    int lane = threadIdx.x & 31;
    if (warp >= NN) return;
    int n = warp;
    float ax = 0.f, ay = 0.f;
    int beg = g_rowptr[n], end = g_rowptr[n + 1];
    for (int j = beg; j < end; j++) {
        int s = g_col[j];
        float2 v = __half22float2(__ldg(&g_bufAh[s * 32 + lane]));
        ax += v.x;
        ay += v.y;
    }
    float2 sv = __half22float2(g_bufAh[n * 32 + lane]);
    ax += sv.x;
    ay += sv.y;
    float di = g_dinv[n];
    float2 b2 = ((const float2*)bias)[lane];
    ax = fmaxf(fmaf(di, ax, b2.x), 0.f);
    ay = fmaxf(fmaf(di, ay, b2.y), 0.f);
    if (!LAST) {
        ((float2*)g_bufB)[n * 32 + lane] = make_float2(ax, ay);
    } else {
        float2 w2 = ((const float2*)Wout)[lane];
        float s = ax * w2.x + ay * w2.y;
        #pragma unroll
        for (int o = 16; o; o >>= 1) s += __shfl_xor_sync(0xffffffffu, s, o);
        if (lane == 0) g_z[n] = di * s;   // pre-scaled zs
    }
}

// ---- final scalar aggregation: out[n] = dinv[n]*(Sum zs[src] + zs[n]) + b ----
__global__ void k_agg_scalar(float* __restrict__ out, const float* __restrict__ b_out) {
    int n = blockIdx.x * blockDim.x + threadIdx.x;
    if (n < NN) {
        float acc = 0.f;
        int beg = g_rowptr[n], end = g_rowptr[n + 1];
        for (int j = beg; j < end; j++) acc += __ldg(&g_z[g_col[j]]);
        acc += g_z[n];
        out[n] = fmaf(g_dinv[n], acc, b_out[0]);
    }
}

// ---------------- launch ------------------------------------------------------
extern "C" void kernel_launch(void* const* d_in, const int* in_sizes, int n_in,
                              void* d_out, int out_size) {
    const float* x     = (const float*)d_in[0];
    const int*   ei    = (const int*)d_in[1];
    const float* W_in  = (const float*)d_in[2];
    const float* b_in  = (const float*)d_in[3];
    const float* W_h   = (const float*)d_in[4];
    const float* b_h   = (const float*)d_in[5];
    const float* W_out = (const float*)d_in[6];
    const float* b_out = (const float*)d_in[7];
    float*       out   = (float*)d_out;

    const int TB = 256;
    const int gN  = (NN + TB - 1) / TB;
    const int gE  = (NE + TB - 1) / TB;
    const int gNF = (NN * HID + TB - 1) / TB;
    const int gW  = (NN * 32 + TB - 1) / TB;
    const int gG  = (NN + 63) / 64;

    // CSR build (+ input pre-scale)
    k_zero_cnt<<<gN, TB>>>();
    k_count<<<gE, TB>>>(ei);
    k_dinv<<<gN, TB>>>(x);
    k_blocksum<<<NB, 256>>>();
    k_scanb<<<1, 1>>>();
    k_scanfinal<<<NB, 1024>>>();
    k_scatter<<<gE, TB>>>(ei);

    // layer 0
    k_agg_x<<<gW, TB>>>();
    k_gemm_in<<<gNF, TB>>>(W_in, b_in);

    // hidden layers 1-2
    for (int l = 0; l < 2; l++) {
        k_gemm64<<<gG, TB>>>(W_h + l * HID * HID);
        k_agg64<false><<<gW, TB>>>(b_h + l * HID, nullptr);
    }
    // hidden layer 3 with fused output GEMM
    k_gemm64<<<gG, TB>>>(W_h + 2 * HID * HID);
    k_agg64<true><<<gW, TB>>>(b_h + 2 * HID, W_out);

    // final scalar aggregation
    k_agg_scalar<<<gN, TB>>>(out, b_out);
}